// round 17
// baseline (speedup 1.0000x reference)
#include <cuda_runtime.h>
#include <cuda_bf16.h>
#include <cstdint>

// ---------------- problem constants ----------------
#define NB    128
#define CIN   1024
#define HH    14
#define WW    14
#define OO    196
#define CF    128
#define TH    128
#define QD    258
#define CED   130
#define PD    388
#define HP    256
#define GT    256
#define FP    256
#define ASZ   32
#define NROWS (NB * OO)     // 25088

// ---------------- scratch ----------------
// NOTE: g_imh/g_iml halo borders rely on CUDA zero-initialization of __device__
// globals; k_prep_all writes interior cells only, nothing ever writes borders.
__device__ __align__(16) __nv_bfloat16 g_imh[NB * 256 * CIN];
__device__ __align__(16) __nv_bfloat16 g_iml[NB * 256 * CIN];
__device__ __align__(16) uint8_t g_wbh[144 * 16384];
__device__ __align__(16) uint8_t g_wbl[144 * 16384];
__device__ __align__(16) float g_xt[NB * OO * CF];
__device__ __align__(16) __nv_bfloat16 g_xth[NB * OO * CF];
__device__ __align__(16) __nv_bfloat16 g_xtl[NB * OO * CF];
__device__ __align__(16) uint8_t g_hpBh[4 * 16384],  g_hpBl[4 * 16384];
__device__ __align__(16) uint8_t g_gt0Bh[4 * 16384], g_gt0Bl[4 * 16384];
__device__ __align__(16) uint8_t g_gt1Bh[8 * 16384], g_gt1Bl[8 * 16384];
__device__ float g_pero_hp[OO * 256], g_pern_hp[NB * 256];
__device__ float g_pero_gt[OO * 256], g_pern_gt[NB * 256];
__device__ float g_att[NB * OO];
__device__ float g_sel[NB * CED];
__device__ float g_rel[NB * GT];

__device__ __forceinline__ float xcoord(int o) { return -1.0f + 2.0f * (float)(o / WW) / 13.0f; }
__device__ __forceinline__ float ycoord(int o) { return -1.0f + 2.0f * (float)(o % WW) / 13.0f; }

// ---------------- helpers ----------------
#define SWZ(x) ((x) ^ (((x) >> 3) & 0x70))

__device__ __forceinline__ uint32_t smem_u32(const void* p) {
    uint32_t a;
    asm("{ .reg .u64 t; cvta.to.shared.u64 t, %1; cvt.u32.u64 %0, t; }" : "=r"(a) : "l"(p));
    return a;
}
__device__ __forceinline__ void ldsm_x4(uint32_t* r, uint32_t addr) {
    asm volatile("ldmatrix.sync.aligned.m8n8.x4.shared.b16 {%0,%1,%2,%3}, [%4];"
                 : "=r"(r[0]), "=r"(r[1]), "=r"(r[2]), "=r"(r[3]) : "r"(addr));
}
__device__ __forceinline__ void mma16816(float* c, const uint32_t* a, uint32_t b0, uint32_t b1) {
    asm volatile("mma.sync.aligned.m16n8k16.row.col.f32.bf16.bf16.f32 "
                 "{%0,%1,%2,%3}, {%4,%5,%6,%7}, {%8,%9}, {%0,%1,%2,%3};"
                 : "+f"(c[0]), "+f"(c[1]), "+f"(c[2]), "+f"(c[3])
                 : "r"(a[0]), "r"(a[1]), "r"(a[2]), "r"(a[3]), "r"(b0), "r"(b1));
}
__device__ __forceinline__ void cp16(uint32_t dst, const void* src) {
    asm volatile("cp.async.cg.shared.global [%0], [%1], 16;" :: "r"(dst), "l"(src));
}
__device__ __forceinline__ void cp_commit() { asm volatile("cp.async.commit_group;" ::: "memory"); }
__device__ __forceinline__ void bf16split(float v, __nv_bfloat16& h, __nv_bfloat16& l) {
    h = __float2bfloat16(v);
    l = __float2bfloat16(v - __bfloat162float(h));
}

// ---------------- mega prep kernel ----------------
#define PREP_BLOCKS 19780

__device__ __forceinline__ void mlppack_one(const float* __restrict__ src,
                                            uint8_t* __restrict__ dstH,
                                            uint8_t* __restrict__ dstL, int idx) {
    int k6    = idx & 63;
    int ch    = (idx >> 6) & 127;
    int chblk = (idx >> 13) & 1;
    int kblk  = idx >> 14;
    float v = src[(kblk * 64 + k6) * 256 + chblk * 128 + ch];
    __nv_bfloat16 hi, lo; bf16split(v, hi, lo);
    int off = (kblk * 2 + chblk) * 16384 + SWZ(ch * 128 + k6 * 2);
    *(__nv_bfloat16*)(dstH + off) = hi;
    *(__nv_bfloat16*)(dstL + off) = lo;
}

__global__ void __launch_bounds__(256) k_prep_all(
    const float* __restrict__ image, const float* __restrict__ conv_w,
    const float* __restrict__ code,
    const float* __restrict__ hp_w0, const float* __restrict__ hp_b0,
    const float* __restrict__ gt_w0, const float* __restrict__ gt_b0,
    const float* __restrict__ gt_w1)
{
    int b = blockIdx.x, tid = threadIdx.x;

    if (b < 4608) {
        int idx = b * 256 + tid;
        int j    = idx & 63;
        int ch   = (idx >> 6) & 127;
        int cb   = (idx >> 13) & 15;
        int kykx = idx >> 17;
        int cin  = cb * 64 + j;
        float v = conv_w[ch * (CIN * 9) + cin * 9 + kykx];
        __nv_bfloat16 hi, lo; bf16split(v, hi, lo);
        int dst = (kykx * 16 + cb) * 16384 + SWZ(ch * 128 + j * 2);
        *(__nv_bfloat16*)(g_wbh + dst) = hi;
        *(__nv_bfloat16*)(g_wbl + dst) = lo;
    } else if (b < 4736) {
        mlppack_one(hp_w0, g_hpBh, g_hpBl, (b - 4608) * 256 + tid);
    } else if (b < 4864) {
        mlppack_one(gt_w0, g_gt0Bh, g_gt0Bl, (b - 4736) * 256 + tid);
    } else if (b < 5120) {
        mlppack_one(gt_w1, g_gt1Bh, g_gt1Bl, (b - 4864) * 256 + tid);
    } else if (b < 19456) {
        int bb = b - 5120;
        int pb = bb % 7, cbk = (bb / 7) % 16, n = bb / 112;
        __shared__ float t[64][33];
        int pos0 = pb * 32;
        for (int e = tid; e < 64 * 32; e += 256) {
            int ci = e >> 5, p = e & 31;
            int pos = pos0 + p;
            float v = 0.0f;
            if (pos < OO) v = image[((size_t)n * CIN + cbk * 64 + ci) * OO + pos];
            t[ci][p] = v;
        }
        __syncthreads();
        for (int e = tid; e < 64 * 32; e += 256) {
            int p = e >> 6, ci = e & 63;
            int pos = pos0 + p;
            if (pos < OO) {
                int row = pos / 14, col = pos - row * 14;
                int hp  = (row + 1) * 16 + (col + 1);
                size_t off = ((size_t)n * 256 + hp) * 1024 + cbk * 64 + ci;
                __nv_bfloat16 hi, lo; bf16split(t[ci][p], hi, lo);
                g_imh[off] = hi;
                g_iml[off] = lo;
            }
        }
    } else if (b < 19652) {
        int o = b - 19456, ch = tid;
        float xc = xcoord(o), yc = ycoord(o);
        g_pero_hp[o * 256 + ch] = xc * hp_w0[128 * 256 + ch] + yc * hp_w0[129 * 256 + ch];
        g_pero_gt[o * 256 + ch] = xc * gt_w0[128 * 256 + ch] + yc * gt_w0[129 * 256 + ch];
    } else {
        int n = b - 19652, ch = tid;
        float sh = hp_b0[ch], sg = gt_b0[ch];
#pragma unroll 4
        for (int d = 0; d < 128; d++) {
            float c = code[n * 128 + d];
            sh = fmaf(c, hp_w0[(130 + d) * 256 + ch], sh);
            sg = fmaf(c, gt_w0[(130 + d) * 256 + ch], sg);
        }
        g_pern_hp[n * 256 + ch] = sh;
        g_pern_gt[n * 256 + ch] = sg;
        g_rel[n * 256 + ch] = 0.0f;
    }
}

// ---------------- conv: global-row unit split, 148 CTAs, 3-stage B ring, 1 sync/stage ----------------
// 25088 rows = 1568 units of 16, zero padding. CTA i owns 10-11 units, <=2 images.
// smem: halo slot0 (H32K,L32K) slot1 (H32K,L32K) | B 3x32K = 224KB + 1K pad = 230400 B.
#define NUNITS 1568
#define NCTA   148
#define CONV_SMEM 230400

__device__ __forceinline__ void prefetch_B3(int g, uint32_t Bb, int tid) {
    int cb = g / 9, kykx = g - cb * 9;
    size_t off = (size_t)(kykx * 16 + cb) * 16384;
    uint32_t dst = Bb + (uint32_t)(g % 3) * 32768;
#pragma unroll
    for (int t = 0; t < 2; t++) {
        int i = tid + t * 512;
        cp16(dst + i * 16,         g_wbh + off + i * 16);
        cp16(dst + 16384 + i * 16, g_wbl + off + i * 16);
    }
}

template<int NMF>
__device__ __forceinline__ void conv_stage(uint32_t haloH, uint32_t haloL, uint32_t Bstage,
                                           int kd, const int* pbA, int chB0, int kHi,
                                           float (*acc)[16]) {
    uint32_t Bh = Bstage, Bl = Bstage + 16384;
#pragma unroll
    for (int ks = 0; ks < 4; ks++) {
        uint32_t bh[2][4], bl[2][4], a[NMF][4];
        uint32_t kof = (uint32_t)(ks * 32 + kHi);
#pragma unroll
        for (int bf = 0; bf < 2; bf++) ldsm_x4(bh[bf], Bh + SWZ((uint32_t)((chB0 + bf * 16) * 128) + kof));
#pragma unroll
        for (int mf = 0; mf < NMF; mf++) ldsm_x4(a[mf], haloH + SWZ((uint32_t)((pbA[mf] + kd) * 128) + kof));
#pragma unroll
        for (int mf = 0; mf < NMF; mf++)
#pragma unroll
            for (int nf = 0; nf < 4; nf++)
                mma16816(&acc[mf][nf * 4], a[mf], bh[nf >> 1][nf & 1], bh[nf >> 1][(nf & 1) + 2]);
#pragma unroll
        for (int bf = 0; bf < 2; bf++) ldsm_x4(bl[bf], Bl + SWZ((uint32_t)((chB0 + bf * 16) * 128) + kof));
#pragma unroll
        for (int mf = 0; mf < NMF; mf++)
#pragma unroll
            for (int nf = 0; nf < 4; nf++)
                mma16816(&acc[mf][nf * 4], a[mf], bl[nf >> 1][nf & 1], bl[nf >> 1][(nf & 1) + 2]);
#pragma unroll
        for (int mf = 0; mf < NMF; mf++) ldsm_x4(a[mf], haloL + SWZ((uint32_t)((pbA[mf] + kd) * 128) + kof));
#pragma unroll
        for (int mf = 0; mf < NMF; mf++)
#pragma unroll
            for (int nf = 0; nf < 4; nf++)
                mma16816(&acc[mf][nf * 4], a[mf], bh[nf >> 1][nf & 1], bh[nf >> 1][(nf & 1) + 2]);
    }
}

// pbA carries slot*512 positions; haloL base = haloH base + 32768.
__device__ __forceinline__ void load_halo(char* sm, int slot, int img, int cb, int tid) {
#pragma unroll
    for (int t = 0; t < 8; t++) {
        int idx = tid + t * 512;
        int half = idx >> 11;
        int j = idx & 2047;
        int p = j >> 3, u = j & 7;
        const __nv_bfloat16* srcp = (half ? g_iml : g_imh) + ((size_t)img * 256 + p) * 1024 + cb * 64;
        uint4 v = ((const uint4*)srcp)[u];
        *(uint4*)(sm + slot * 65536 + half * 32768 + SWZ(p * 128 + u * 16)) = v;
    }
}

__global__ void __launch_bounds__(512) k_conv_mma(const float* __restrict__ conv_b) {
    extern __shared__ char sm_raw[];
    __shared__ float s_bias[128];
    const int tid = threadIdx.x;
    const int wid = tid >> 5, lane = tid & 31;
    const int wm = wid >> 2, wn = wid & 3;

    const int u0 = (blockIdx.x * NUNITS) / NCTA;
    const int u1 = ((blockIdx.x + 1) * NUNITS) / NCTA;
    const int cnt = u1 - u0;
    const int n0 = (u0 * 16) / OO;
    const int n1 = (u1 * 16 - 1) / OO;
    const int two = (n1 != n0);
    const int nmf = (cnt - wm + 3) >> 2;

    uint32_t raw = smem_u32(sm_raw);
    uint32_t base = (raw + 1023u) & ~1023u;
    char* sm = sm_raw + (base - raw);
    const uint32_t Bb = base + 131072;

    if (tid < 128) s_bias[tid] = conv_b[tid];

    float acc[3][16];
#pragma unroll
    for (int i = 0; i < 3; i++)
#pragma unroll
        for (int j = 0; j < 16; j++) acc[i][j] = 0.0f;

    int pbA[3], uG[3];
#pragma unroll
    for (int mf = 0; mf < 3; mf++) {
        int uu = u0 + wm + 4 * mf;
        if (uu >= u1) uu = u1 - 1;
        uG[mf] = uu;
        int r = uu * 16 + (lane & 15);
        int nn = r / OO, oo = r - nn * OO;
        int row = oo / 14, col = oo - row * 14;
        pbA[mf] = (nn - n0) * 512 + row * 16 + col;
    }
    const int kHi = (lane >> 4) * 16;
    const int chB0 = wn * 32 + (lane & 15);

    prefetch_B3(0, Bb, tid); cp_commit();
    prefetch_B3(1, Bb, tid); cp_commit();

    for (int gs = 0; gs < 144; gs++) {
        int cb = gs / 9, kykx = gs - cb * 9;
        if (kykx == 0) {
            __syncthreads();                 // old halo reads done
            load_halo(sm, 0, n0, cb, tid);
            if (two) load_halo(sm, 1, n1, cb, tid);
        }
        if (gs < 143) asm volatile("cp.async.wait_group 1;" ::: "memory");
        else          asm volatile("cp.async.wait_group 0;" ::: "memory");
        __syncthreads();                     // publish B(gs)+halo; slot (gs-1)%3 free
        if (gs + 2 < 144) { prefetch_B3(gs + 2, Bb, tid); cp_commit(); }

        int ky = kykx / 3, kx = kykx - ky * 3;
        int kd = ky * 16 + kx;
        uint32_t Bst = Bb + (uint32_t)(gs % 3) * 32768;

        if (nmf == 3) conv_stage<3>(base, base + 32768, Bst, kd, pbA, chB0, kHi, acc);
        else          conv_stage<2>(base, base + 32768, Bst, kd, pbA, chB0, kHi, acc);
    }

    int g = lane >> 2, t2 = (lane & 3) * 2;
#pragma unroll
    for (int mf = 0; mf < 3; mf++) {
        if (mf < nmf) {
#pragma unroll
            for (int nf = 0; nf < 4; nf++) {
                int ch = wn * 32 + nf * 8 + t2;
                float b0 = s_bias[ch], b1 = s_bias[ch + 1];
#pragma unroll
                for (int h = 0; h < 2; h++) {
                    int r = uG[mf] * 16 + g + h * 8;
                    float v0 = acc[mf][nf * 4 + h * 2 + 0] + b0;
                    float v1 = acc[mf][nf * 4 + h * 2 + 1] + b1;
                    g_xt[(size_t)r * CF + ch]     = v0;
                    g_xt[(size_t)r * CF + ch + 1] = v1;
                    __nv_bfloat16 h0, l0, h1, l1;
                    bf16split(v0, h0, l0);
                    bf16split(v1, h1, l1);
                    *(__nv_bfloat162*)(g_xth + (size_t)r * CF + ch) = __nv_bfloat162{h0, h1};
                    *(__nv_bfloat162*)(g_xtl + (size_t)r * CF + ch) = __nv_bfloat162{l0, l1};
                }
            }
        }
    }
}

// ---------------- M=96 GEMM machinery ----------------
#define GM    96
#define NT96  262
#define A_ATOM 12288

__device__ __forceinline__ void gemm_stage96(float (*acc)[16], uint32_t AhT, uint32_t AlT,
                                             uint32_t Bt, bool doLo,
                                             const uint32_t* rbase, uint32_t chbase, uint32_t kHi) {
#pragma unroll
    for (int ks = 0; ks < 4; ks++) {
        uint32_t b[2][4];
        ldsm_x4(b[0], Bt + SWZ(chbase + ks * 32 + kHi));
        ldsm_x4(b[1], Bt + SWZ(chbase + 16 * 128 + ks * 32 + kHi));
#pragma unroll
        for (int mf = 0; mf < 3; mf++) {
            uint32_t a[4];
            ldsm_x4(a, AhT + SWZ(rbase[mf] + ks * 32 + kHi));
#pragma unroll
            for (int nf = 0; nf < 4; nf++)
                mma16816(&acc[mf][nf * 4], a,
                         (nf & 1) ? b[nf >> 1][1] : b[nf >> 1][0],
                         (nf & 1) ? b[nf >> 1][3] : b[nf >> 1][2]);
            if (doLo) {
                uint32_t al[4];
                ldsm_x4(al, AlT + SWZ(rbase[mf] + ks * 32 + kHi));
#pragma unroll
                for (int nf = 0; nf < 4; nf++)
                    mma16816(&acc[mf][nf * 4], al,
                             (nf & 1) ? b[nf >> 1][1] : b[nf >> 1][0],
                             (nf & 1) ? b[nf >> 1][3] : b[nf >> 1][2]);
            }
        }
    }
}

__device__ __forceinline__ void load_A_tile96(uint32_t smb, int r0, int tid) {
#pragma unroll
    for (int t = 0; t < 6; t++) {
        int idx = tid + t * 512;
        int half = idx >= 1536;
        int j = idx - half * 1536;
        int row = j >> 4, cc = j & 15;
        int kblk = cc >> 3, u = cc & 7;
        int rr = r0 + row; if (rr >= NROWS) rr = NROWS - 1;
        const __nv_bfloat16* src = (half ? g_xtl : g_xth) + (size_t)rr * 128 + kblk * 64 + u * 8;
        cp16(smb + half * 24576 + kblk * A_ATOM + SWZ(row * 128 + u * 16), src);
    }
}

// ---------------- h_psi as GEMM (262 M=96 tiles) ----------------
__global__ void __launch_bounds__(512) k_hpsi_mma(const float* __restrict__ hp_w1,
                                                  const float* __restrict__ hp_b1) {
    extern __shared__ char sm_raw[];
    __shared__ float s_w1[256];
    __shared__ float attp[8][GM];

    const int tid = threadIdx.x;
    const int r0 = blockIdx.x * GM;
    const int wid = tid >> 5, lane = tid & 31;
    const int wm = wid & 1, wn = wid >> 1;

    uint32_t raw = smem_u32(sm_raw);
    uint32_t smb = (raw + 1023u) & ~1023u;
    const uint32_t Bbuf = smb + 49152;

    if (tid < 256) s_w1[tid] = hp_w1[tid];

    uint32_t rbase[3];
#pragma unroll
    for (int mf = 0; mf < 3; mf++) rbase[mf] = (uint32_t)(wm * 48 + mf * 16 + (lane & 15)) * 128;
    const uint32_t kHi = (lane >> 4) * 16;
    const uint32_t chbase = (uint32_t)((wn & 3) * 32 + (lane & 15)) * 128;
    const uint32_t Bwn = (wn >> 2) * 16384;

    float acc[3][16];
#pragma unroll
    for (int i = 0; i < 3; i++)
#pragma unroll
        for (int j = 0; j < 16; j++) acc[i][j] = 0.0f;

    {
        const uint8_t* src = g_hpBh;
#pragma unroll
        for (int t = 0; t < 4; t++) cp16(Bbuf + (tid + t * 512) * 16, src + (tid + t * 512) * 16);
        load_A_tile96(smb, r0, tid);
        cp_commit();
    }

    for (int s = 0; s < 4; s++) {
        if (s < 3) {
            int sn = s + 1;
            const uint8_t* src = ((sn & 1) ? g_hpBl : g_hpBh) + (size_t)(sn >> 1) * 32768;
            uint32_t dstb = Bbuf + (sn & 1) * 32768;
#pragma unroll
            for (int t = 0; t < 4; t++) cp16(dstb + (tid + t * 512) * 16, src + (tid + t * 512) * 16);
            cp_commit();
            asm volatile("cp.async.wait_group 1;" ::: "memory");
        } else {
            asm volatile("cp.async.wait_group 0;" ::: "memory");
        }
        __syncthreads();
        int kblk = s >> 1;
        gemm_stage96(acc, smb + kblk * A_ATOM, smb + 24576 + kblk * A_ATOM,
                     Bbuf + (s & 1) * 32768 + Bwn, (s & 1) == 0, rbase, chbase, kHi);
        __syncthreads();
    }

    int g = lane >> 2, t2 = (lane & 3) * 2;
    float psum[3][2];
#pragma unroll
    for (int mf = 0; mf < 3; mf++) { psum[mf][0] = 0.0f; psum[mf][1] = 0.0f; }
#pragma unroll
    for (int mf = 0; mf < 3; mf++)
#pragma unroll
        for (int h = 0; h < 2; h++) {
            int row = wm * 48 + mf * 16 + g + h * 8;
            int r = r0 + row; if (r >= NROWS) r = NROWS - 1;
            int n = r / OO, o = r - n * OO;
#pragma unroll
            for (int nf = 0; nf < 4; nf++)
#pragma unroll
                for (int j = 0; j < 2; j++) {
                    int ch = wn * 32 + nf * 8 + t2 + j;
                    float v = acc[mf][nf * 4 + h * 2 + j] + g_pero_hp[o * 256 + ch] + g_pern_hp[n * 256 + ch];
                    psum[mf][h] += fmaxf(v, 0.0f) * s_w1[ch];
                }
        }
#pragma unroll
    for (int mf = 0; mf < 3; mf++)
#pragma unroll
        for (int h = 0; h < 2; h++) {
            float p = psum[mf][h];
            p += __shfl_xor_sync(0xffffffffu, p, 1);
            p += __shfl_xor_sync(0xffffffffu, p, 2);
            if ((lane & 3) == 0) attp[wn][wm * 48 + mf * 16 + g + h * 8] = p;
        }
    __syncthreads();
    if (tid < GM && r0 + tid < NROWS) {
        float a = hp_b1[0];
#pragma unroll
        for (int w = 0; w < 8; w++) a += attp[w][tid];
        g_att[r0 + tid] = a;
    }
}

// ---------------- fused g_theta (262 M=96 tiles) ----------------
__global__ void __launch_bounds__(512) k_gt_mma(const float* __restrict__ gt_b1) {
    extern __shared__ char sm_raw[];
    __shared__ float s_b1[256];
    __shared__ float relp[2][256];

    const int tid = threadIdx.x;
    const int r0 = blockIdx.x * GM;
    const int wid = tid >> 5, lane = tid & 31;
    const int wm = wid & 1, wn = wid >> 1;

    uint32_t raw = smem_u32(sm_raw);
    uint32_t smb = (raw + 1023u) & ~1023u;
    const uint32_t A2h = smb + 49152, A2l = smb + 98304;
    const uint32_t Bbuf = smb + 147456;

    if (tid < 256) s_b1[tid] = gt_b1[tid];
    if (tid < 512) ((float*)relp)[tid] = 0.0f;

    uint32_t rbase[3];
#pragma unroll
    for (int mf = 0; mf < 3; mf++) rbase[mf] = (uint32_t)(wm * 48 + mf * 16 + (lane & 15)) * 128;
    const uint32_t kHi = (lane >> 4) * 16;
    const uint32_t chbase = (uint32_t)((wn & 3) * 32 + (lane & 15)) * 128;
    const uint32_t Bwn = (wn >> 2) * 16384;
    const int g = lane >> 2, t2 = (lane & 3) * 2;

    float acc[3][16];
#pragma unroll
    for (int i = 0; i < 3; i++)
#pragma unroll
        for (int j = 0; j < 16; j++) acc[i][j] = 0.0f;

    {
#pragma unroll
        for (int t = 0; t < 4; t++) cp16(Bbuf + (tid + t * 512) * 16, g_gt0Bh + (tid + t * 512) * 16);
        load_A_tile96(smb, r0, tid);
        cp_commit();
    }

    for (int s = 0; s < 12; s++) {
        if (s < 11) {
            int sn = s + 1;
            const uint8_t* basep;
            int kblk;
            if (sn < 4) { basep = (sn & 1) ? g_gt0Bl : g_gt0Bh; kblk = sn >> 1; }
            else        { int t = sn - 4; basep = (t & 1) ? g_gt1Bl : g_gt1Bh; kblk = t >> 1; }
            const uint8_t* src = basep + (size_t)kblk * 32768;
            uint32_t dstb = Bbuf + (sn & 1) * 32768;
#pragma unroll
            for (int t = 0; t < 4; t++) cp16(dstb + (tid + t * 512) * 16, src + (tid + t * 512) * 16);
            cp_commit();
            asm volatile("cp.async.wait_group 1;" ::: "memory");
        } else {
            asm volatile("cp.async.wait_group 0;" ::: "memory");
        }
        __syncthreads();

        if (s < 4) {
            int kblk = s >> 1;
            gemm_stage96(acc, smb + kblk * A_ATOM, smb + 24576 + kblk * A_ATOM,
                         Bbuf + (s & 1) * 32768 + Bwn, (s & 1) == 0, rbase, chbase, kHi);
        } else {
            int kt = (s - 4) >> 1;
            gemm_stage96(acc, A2h + kt * A_ATOM, A2l + kt * A_ATOM,
                         Bbuf + (s & 1) * 32768 + Bwn, (s & 1) == 0, rbase, chbase, kHi);
        }
        __syncthreads();

        if (s == 3) {
#pragma unroll
            for (int mf = 0; mf < 3; mf++)
#pragma unroll
                for (int h = 0; h < 2; h++) {
                    int row = wm * 48 + mf * 16 + g + h * 8;
                    int r = r0 + row; if (r >= NROWS) r = NROWS - 1;
                    int n = r / OO, o = r - n * OO;
#pragma unroll
                    for (int nf = 0; nf < 4; nf++) {
                        int ch0 = wn * 32 + nf * 8 + t2;
                        float v0 = acc[mf][nf * 4 + h * 2 + 0] + g_pero_gt[o * 256 + ch0]     + g_pern_gt[n * 256 + ch0];
                        float v1 = acc[mf][nf * 4 + h * 2 + 1] + g_pero_gt[o * 256 + ch0 + 1] + g_pern_gt[n * 256 + ch0 + 1];
                        v0 = fmaxf(v0, 0.0f); v1 = fmaxf(v1, 0.0f);
                        __nv_bfloat16 h0, l0, h1, l1;
                        bf16split(v0, h0, l0);
                        bf16split(v1, h1, l1);
                        uint32_t off = (uint32_t)(ch0 >> 6) * A_ATOM + SWZ(row * 128 + (ch0 & 63) * 2);
                        *(__nv_bfloat162*)(sm_raw + (A2h - raw) + off) = __nv_bfloat162{h0, h1};
                        *(__nv_bfloat162*)(sm_raw + (A2l - raw) + off) = __nv_bfloat162{l0, l1};
                    }
                }
#pragma unroll
            for (int i = 0; i < 3; i++)
#pragma unroll
                for (int j = 0; j < 16; j++) acc[i][j] = 0.0f;
            __syncthreads();
        }
    }

    int rlast = r0 + GM - 1; if (rlast >= NROWS) rlast = NROWS - 1;
    const int n0 = r0 / OO;
    const int n1 = rlast / OO;
#pragma unroll
    for (int mf = 0; mf < 3; mf++)
#pragma unroll
        for (int h = 0; h < 2; h++) {
            int row = wm * 48 + mf * 16 + g + h * 8;
            int r = r0 + row;
            if (r < NROWS) {
                int n = r / OO;
                int nn = (n != n0);
#pragma unroll
                for (int nf = 0; nf < 4; nf++)
#pragma unroll
                    for (int j = 0; j < 2; j++) {
                        int ch = wn * 32 + nf * 8 + t2 + j;
                        float v = fmaxf(acc[mf][nf * 4 + h * 2 + j] + s_b1[ch], 0.0f);
                        atomicAdd(&relp[nn][ch], v);
                    }
            }
        }
    __syncthreads();
    if (tid < 256) {
        atomicAdd(&g_rel[n0 * 256 + tid], relp[0][tid]);
    } else {
        int ch = tid - 256;
        if (n1 != n0) atomicAdd(&g_rel[n1 * 256 + ch], relp[1][ch]);
    }
}

// ---------------- softmax + soft selection (float4) + pern_gt finish ----------------
__global__ void __launch_bounds__(512) k_softsel(const float* __restrict__ gt_w0) {
    int n = blockIdx.x;
    int tid = threadIdx.x;
    __shared__ float att_s[OO];
    __shared__ float red_s[16];
    __shared__ float selp[16][128];
    __shared__ float sel_s[CED];
    __shared__ float pgp[2][256];

    if (tid < OO) att_s[tid] = g_att[n * OO + tid];
    __syncthreads();

    float v = (tid < OO) ? att_s[tid] : -1e30f;
#pragma unroll
    for (int off = 16; off > 0; off >>= 1) v = fmaxf(v, __shfl_xor_sync(0xffffffffu, v, off));
    if ((tid & 31) == 0) red_s[tid >> 5] = v;
    __syncthreads();
    float m = -1e30f;
#pragma unroll
    for (int i = 0; i < 16; i++) m = fmaxf(m, red_s[i]);
    __syncthreads();

    float e = (tid < OO) ? expf(att_s[tid] - m) : 0.0f;
    float sv = e;
#pragma unroll
    for (int off = 16; off > 0; off >>= 1) sv += __shfl_xor_sync(0xffffffffu, sv, off);
    if ((tid & 31) == 0) red_s[tid >> 5] = sv;
    __syncthreads();
    float tot = 0.0f;
#pragma unroll
    for (int i = 0; i < 16; i++) tot += red_s[i];
    if (tid < OO) att_s[tid] = e / tot;
    __syncthreads();

    // selection: og = tid>>5 (16 o-groups: first 4 get 13, rest 12), dq = tid&31 (float4 of d)
    {
        const float* xtn = g_xt + (size_t)n * OO * CF;
        int og = tid >> 5, dq = tid & 31;
        int o0  = (og < 4) ? og * 13 : 52 + (og - 4) * 12;
        int cnt = (og < 4) ? 13 : 12;
        float4 a0 = {0, 0, 0, 0}, a1 = {0, 0, 0, 0};
        for (int i = 0; i + 1 < cnt; i += 2) {
            float w0 = att_s[o0 + i], w1 = att_s[o0 + i + 1];
            float4 x0 = *(const float4*)(xtn + (size_t)(o0 + i)     * CF + dq * 4);
            float4 x1 = *(const float4*)(xtn + (size_t)(o0 + i + 1) * CF + dq * 4);
            a0.x = fmaf(w0, x0.x, a0.x); a0.y = fmaf(w0, x0.y, a0.y);
            a0.z = fmaf(w0, x0.z, a0.z); a0.w = fmaf(w0, x0.w, a0.w);
            a1.x = fmaf(w1, x1.x, a1.x); a1.y = fmaf(w1, x1.y, a1.y);
            a1.z = fmaf(w1, x1.z, a1.z); a1.w = fmaf(w1, x1.w, a1.w);
        }
        if (cnt & 1) {
            float w0 = att_s[o0 + cnt - 1];
            float4 x0 = *(const float4*)(xtn + (size_t)(o0 + cnt - 1) * CF + dq * 4);
            a0.x = fmaf(w0, x0.x, a0.x); a0.y = fmaf(w0, x0.y, a0.y);
            a0.z = fmaf(w0, x0.z, a0.z); a0.w = fmaf(w0, x0.w, a0.w);
        }
        selp[og][dq * 4 + 0] = a0.x + a1.x;
        selp[og][dq * 4 + 1] = a0.y + a1.y;
        selp[og][dq * 4 + 2] = a0.z + a1.z;
        selp[og][dq * 4 + 3] = a0.w + a1.w;
    }
    __syncthreads();
    if (tid < 128) {
        float s = 0.0f;
#pragma unroll
        for (int og = 0; og < 16; og++) s += selp[og][tid];
        g_sel[n * CED + tid] = s;
        sel_s[tid] = s;
    } else if (tid == 128) {
        float a = 0.0f;
        for (int o = 0; o < OO; o++) a = fmaf(att_s[o], xcoord(o), a);
        g_sel[n * CED + 128] = a;
        sel_s[128] = a;
    } else if (tid == 129) {
        float a = 0.0f;
        for (int o = 0; o < OO; o++) a = fmaf(att_s[o], ycoord(o), a);
        g_sel[n * CED + 129] = a;
        sel_s[129] = a;
    }
    __syncthreads();

    {
        int p = tid >> 8, ch = tid & 255;
        int d0 = p * 65, d1 = d0 + 65;
        float s = 0.0f;
#pragma unroll 4
        for (int d = d0; d < d1; d++)
            s = fmaf(sel_s[d], gt_w0[(QD + d) * 256 + ch], s);
        pgp[p][ch] = s;
    }
    __syncthreads();
    if (tid < 256)
        g_pern_gt[n * 256 + tid] += pgp[0][tid] + pgp[1][tid];
}

// ---------------- f_phi head ----------------
__global__ void __launch_bounds__(256) k_fphi(const float* __restrict__ fp_w0,
                                              const float* __restrict__ fp_b0,
                                              const float* __restrict__ fp_w1,
                                              const float* __restrict__ fp_b1,
                                              float* __restrict__ out) {
    int n = blockIdx.x;
    int tid = threadIdx.x;
    __shared__ float f_s[FP];

    const float* rel = g_rel + n * GT;
    float s = fp_b0[tid];
#pragma unroll 4
    for (int h = 0; h < GT; h++)
        s = fmaf(rel[h], fp_w0[h * FP + tid], s);
    f_s[tid] = fmaxf(s, 0.0f);
    __syncthreads();

    if (tid < ASZ) {
        float s2 = fp_b1[tid];
#pragma unroll 4
        for (int h = 0; h < FP; h++)
            s2 = fmaf(f_s[h], fp_w1[h * ASZ + tid], s2);
        out[n * ASZ + tid] = s2;
    }
}

// ---------------- launch ----------------
extern "C" void kernel_launch(void* const* d_in, const int* in_sizes, int n_in,
                              void* d_out, int out_size) {
    const float* image  = (const float*)d_in[0];
    const float* code   = (const float*)d_in[1];
    const float* conv_w = (const float*)d_in[2];
    const float* conv_b = (const float*)d_in[3];
    const float* hp_w0  = (const float*)d_in[4];
    const float* hp_b0  = (const float*)d_in[5];
    const float* hp_w1  = (const float*)d_in[6];
    const float* hp_b1  = (const float*)d_in[7];
    const float* gt_w0  = (const float*)d_in[8];
    const float* gt_b0  = (const float*)d_in[9];
    const float* gt_w1  = (const float*)d_in[10];
    const float* gt_b1  = (const float*)d_in[11];
    const float* fp_w0  = (const float*)d_in[12];
    const float* fp_b0  = (const float*)d_in[13];
    const float* fp_w1  = (const float*)d_in[14];
    const float* fp_b1  = (const float*)d_in[15];
    float* out = (float*)d_out;

    cudaFuncSetAttribute(k_conv_mma, cudaFuncAttributeMaxDynamicSharedMemorySize, CONV_SMEM);
    cudaFuncSetAttribute(k_hpsi_mma, cudaFuncAttributeMaxDynamicSharedMemorySize, 115712);
    cudaFuncSetAttribute(k_gt_mma,   cudaFuncAttributeMaxDynamicSharedMemorySize, 214016);

    k_prep_all<<<PREP_BLOCKS, 256>>>(image, conv_w, code, hp_w0, hp_b0, gt_w0, gt_b0, gt_w1);
    k_conv_mma<<<NCTA, 512, CONV_SMEM>>>(conv_b);
    k_hpsi_mma<<<NT96, 512, 115712>>>(hp_w1, hp_b1);
    k_softsel<<<NB, 512>>>(gt_w0);
    k_gt_mma<<<NT96, 512, 214016>>>(gt_b1);
    k_fphi<<<NB, 256>>>(fp_w0, fp_b0, fp_w1, fp_b1, out);
}